// round 1
// baseline (speedup 1.0000x reference)
#include <cuda_runtime.h>

#define NTOK 49
#define CDIM 128
#define HEADS 4
#define HD 32
#define THREADS 384

static constexpr float SCALE = 0.17677669529663687f; // 32^-0.5

// smem layout (floats):
//   s_x   : [128][52]  transposed x (phase 1/2); overlaid by o_nc [49][132] in phase 3/4
//   s_qkv : [49][388]  qkv activations (q:0..127, k:128..255, v:256..383)
//   s_msk : [49*49]    shift mask for this window
#define SX_STRIDE   52
#define QKV_STRIDE  388
#define ONC_STRIDE  132
#define SX_FLOATS   (128 * SX_STRIDE)            // 6656
#define QKV_FLOATS  (NTOK * QKV_STRIDE)          // 19012
#define MSK_FLOATS  (NTOK * NTOK)                // 2401
#define SMEM_FLOATS (SX_FLOATS + QKV_FLOATS + MSK_FLOATS)
#define SMEM_BYTES  (SMEM_FLOATS * 4)            // 112276 B

typedef unsigned long long ull;

__device__ __forceinline__ ull pk2(float lo, float hi) {
    ull r; asm("mov.b64 %0, {%1, %2};" : "=l"(r) : "f"(lo), "f"(hi)); return r;
}
__device__ __forceinline__ void upk2(ull v, float& lo, float& hi) {
    asm("mov.b64 {%0, %1}, %2;" : "=f"(lo), "=f"(hi) : "l"(v));
}
__device__ __forceinline__ ull fma2(ull a, ull b, ull c) {
    ull d; asm("fma.rn.f32x2 %0, %1, %2, %3;" : "=l"(d) : "l"(a), "l"(b), "l"(c)); return d;
}

__global__ void __launch_bounds__(THREADS)
win_attn_kernel(const float* __restrict__ x,
                const float* __restrict__ qkv_w,
                const float* __restrict__ proj_w,
                const float* __restrict__ proj_b,
                const float* __restrict__ table,
                const float* __restrict__ mask,
                const int*   __restrict__ pidx,
                float* __restrict__ out,
                int nW)
{
    extern __shared__ float smem[];
    float* s_x   = smem;                  // [128][52], later o_nc [49][132]
    float* s_qkv = smem + SX_FLOATS;      // [49][388]
    float* s_msk = s_qkv + QKV_FLOATS;    // [49*49]

    const int b = blockIdx.x;
    const int t = threadIdx.x;

    // ---------------- Phase 1: load x (transposed) + mask ----------------
    {
        const float4* x4 = (const float4*)(x + (size_t)b * NTOK * CDIM);
        #pragma unroll 1
        for (int i = t; i < NTOK * CDIM / 4; i += THREADS) {
            float4 v = __ldg(x4 + i);
            int n  = i >> 5;            // 32 float4 per token row
            int c4 = (i & 31) << 2;
            s_x[(c4 + 0) * SX_STRIDE + n] = v.x;
            s_x[(c4 + 1) * SX_STRIDE + n] = v.y;
            s_x[(c4 + 2) * SX_STRIDE + n] = v.z;
            s_x[(c4 + 3) * SX_STRIDE + n] = v.w;
        }
        const float* mrow = mask + (size_t)(b % nW) * NTOK * NTOK;
        #pragma unroll 1
        for (int i = t; i < NTOK * NTOK; i += THREADS)
            s_msk[i] = __ldg(mrow + i);
    }
    __syncthreads();

    // ---------------- Phase 2: qkv = x @ qkv_w^T, thread t = column o=t ----
    {
        ull a2[24];
        float a48 = 0.f;
        #pragma unroll
        for (int i = 0; i < 24; i++) a2[i] = 0ull;

        const float4* w4p = (const float4*)(qkv_w + t * CDIM);
        #pragma unroll 2
        for (int cc = 0; cc < 32; cc++) {
            float4 w4 = __ldg(w4p + cc);
            #pragma unroll
            for (int j = 0; j < 4; j++) {
                float wv = (&w4.x)[j];
                ull wv2 = pk2(wv, wv);
                const int c = cc * 4 + j;
                const ulonglong2* xr = (const ulonglong2*)(s_x + c * SX_STRIDE);
                #pragma unroll
                for (int q = 0; q < 12; q++) {
                    ulonglong2 xv = xr[q];
                    a2[2 * q]     = fma2(wv2, xv.x, a2[2 * q]);
                    a2[2 * q + 1] = fma2(wv2, xv.y, a2[2 * q + 1]);
                }
                a48 = fmaf(wv, s_x[c * SX_STRIDE + 48], a48);
            }
        }
        #pragma unroll
        for (int i = 0; i < 24; i++) {
            float lo, hi; upk2(a2[i], lo, hi);
            s_qkv[(2 * i) * QKV_STRIDE + t]     = lo;
            s_qkv[(2 * i + 1) * QKV_STRIDE + t] = hi;
        }
        s_qkv[48 * QKV_STRIDE + t] = a48;
    }
    __syncthreads();

    // ---------------- Phase 3: attention per (head, row) -------------------
    if (t < HEADS * NTOK) {
        const int h = t / NTOK;
        const int n = t % NTOK;

        // pack q row into registers
        ull q2[16];
        {
            const ulonglong2* qrow = (const ulonglong2*)(s_qkv + n * QKV_STRIDE + h * HD);
            #pragma unroll
            for (int i = 0; i < 8; i++) {
                ulonglong2 v = qrow[i];
                q2[2 * i] = v.x; q2[2 * i + 1] = v.y;
            }
        }

        float p[NTOK];
        float mx = -1e30f;
        const int*   prow  = pidx + n * NTOK;
        const float* mkrow = s_msk + n * NTOK;

        #pragma unroll
        for (int m = 0; m < NTOK; m++) {
            const ulonglong2* krow =
                (const ulonglong2*)(s_qkv + m * QKV_STRIDE + CDIM + h * HD);
            ull sa = 0ull, sb = 0ull;
            #pragma unroll
            for (int i = 0; i < 8; i++) {
                ulonglong2 kv = krow[i];
                sa = fma2(q2[2 * i],     kv.x, sa);
                sb = fma2(q2[2 * i + 1], kv.y, sb);
            }
            float a0, a1, b0, b1; upk2(sa, a0, a1); upk2(sb, b0, b1);
            float dot = (a0 + a1) + (b0 + b1);
            int id = __ldg(prow + m);
            float s = fmaf(dot, SCALE, __ldg(table + id * 4 + h) + mkrow[m]);
            p[m] = s;
            mx = fmaxf(mx, s);
        }

        float sum = 0.f;
        #pragma unroll
        for (int m = 0; m < NTOK; m++) { p[m] = __expf(p[m] - mx); sum += p[m]; }
        float inv = 1.0f / sum;

        ull acc[16];
        #pragma unroll
        for (int i = 0; i < 16; i++) acc[i] = 0ull;
        #pragma unroll
        for (int m = 0; m < NTOK; m++) {
            ull pm2 = pk2(p[m], p[m]);
            const ulonglong2* vrow =
                (const ulonglong2*)(s_qkv + m * QKV_STRIDE + 2 * CDIM + h * HD);
            #pragma unroll
            for (int i = 0; i < 8; i++) {
                ulonglong2 vv = vrow[i];
                acc[2 * i]     = fma2(pm2, vv.x, acc[2 * i]);
                acc[2 * i + 1] = fma2(pm2, vv.y, acc[2 * i + 1]);
            }
        }

        float* orow = s_x + n * ONC_STRIDE + h * HD;   // o_nc overlay (x tile is dead)
        #pragma unroll
        for (int i = 0; i < 16; i++) {
            float lo, hi; upk2(acc[i], lo, hi);
            orow[2 * i]     = lo * inv;
            orow[2 * i + 1] = hi * inv;
        }
    }
    __syncthreads();

    // ---------------- Phase 4: out = o @ proj_w^T + b ----------------------
    {
        const int o  = t & 127;
        const int g  = t >> 7;            // 0,1,2
        const int n0 = g * 17;            // rows n0..n0+16 (g=2: only 15 valid, reads safe)

        ull acc[17];
        #pragma unroll
        for (int i = 0; i < 17; i++) acc[i] = 0ull;

        const float4* w4p = (const float4*)(proj_w + o * CDIM);
        #pragma unroll 2
        for (int cc = 0; cc < 32; cc++) {
            float4 w4 = __ldg(w4p + cc);
            ull wp0 = pk2(w4.x, w4.y);
            ull wp1 = pk2(w4.z, w4.w);
            #pragma unroll
            for (int i = 0; i < 17; i++) {
                ulonglong2 xv = ((const ulonglong2*)(s_x + (n0 + i) * ONC_STRIDE))[cc];
                acc[i] = fma2(wp0, xv.x, acc[i]);
                acc[i] = fma2(wp1, xv.y, acc[i]);
            }
        }

        float bias = __ldg(proj_b + o);
        float* obase = out + (size_t)b * NTOK * CDIM;
        #pragma unroll
        for (int i = 0; i < 17; i++) {
            int n = n0 + i;
            if (n < NTOK) {
                float lo, hi; upk2(acc[i], lo, hi);
                obase[n * CDIM + o] = lo + hi + bias;
            }
        }
    }
}

extern "C" void kernel_launch(void* const* d_in, const int* in_sizes, int n_in,
                              void* d_out, int out_size)
{
    const float* x      = (const float*)d_in[0];
    const float* qkv_w  = (const float*)d_in[1];
    const float* proj_w = (const float*)d_in[2];
    const float* proj_b = (const float*)d_in[3];
    const float* table  = (const float*)d_in[4];
    const float* mask   = (const float*)d_in[5];
    const int*   pidx   = (const int*)d_in[6];
    float* out = (float*)d_out;

    int B  = in_sizes[0] / (NTOK * CDIM);      // 8192
    int nW = in_sizes[5] / (NTOK * NTOK);      // 1024

    cudaFuncSetAttribute(win_attn_kernel,
                         cudaFuncAttributeMaxDynamicSharedMemorySize, SMEM_BYTES);
    win_attn_kernel<<<B, THREADS, SMEM_BYTES>>>(x, qkv_w, proj_w, proj_b,
                                                table, mask, pidx, out, nW);
}